// round 7
// baseline (speedup 1.0000x reference)
#include <cuda_runtime.h>
#include <utility>
#include <cstdint>

// x[262144, 16] -> out[262144, 696]
// 696 = 16 identity + C(16,2)=120 pairs + C(16,3)=560 triples (lexicographic).
#define NC       16
#define N_OUT4   174      // 696 / 4 float4 per row
#define BLOCK    256      // threads per block == rows per block (8 warps)
#define CHUNK    8        // float4 columns staged per chunk
#define NCHUNK   22       // ceil(174 / 8); last chunk has 6 float4
#define RSTRIDE  36       // floats per staged row (32 data + 4 pad: conflict-free)

// ---------------------------------------------------------------------------
// Compile-time subset index for output column c (lexicographic, matches
// itertools.combinations). j/k == -1 means "absent".
// ---------------------------------------------------------------------------
struct Idx3 { int i, j, k; };

__host__ __device__ constexpr Idx3 col_idx(int c) {
    if (c < NC) return Idx3{c, -1, -1};
    int p = NC;
    for (int i = 0; i < NC; i++)
        for (int j = i + 1; j < NC; j++) {
            if (c == p) return Idx3{i, j, -1};
            p++;
        }
    for (int i = 0; i < NC; i++)
        for (int j = i + 1; j < NC; j++)
            for (int k = j + 1; k < NC; k++) {
                if (c == p) return Idx3{i, j, k};
                p++;
            }
    return Idx3{0, 0, 0};
}

// Product for column C: all-register FMULs, indices folded at compile time.
template<int C>
__device__ __forceinline__ float val(const float* xv) {
    constexpr Idx3 t = col_idx(C);
    float v = xv[t.i];
    if constexpr (t.j >= 0) v *= xv[t.j];
    if constexpr (t.k >= 0) v *= xv[t.k];
    return v;
}

// Compute + stage this lane's row slice for chunk CH (interleaved STS keeps
// the live register set small).
template<int CH, int... Is>
__device__ __forceinline__ void compute_chunk(const float* xv, float* lanerow,
                                              std::integer_sequence<int, Is...>) {
    ((*reinterpret_cast<float4*>(lanerow + Is * 4) =
          make_float4(val<(CH * CHUNK + Is) * 4 + 0>(xv),
                      val<(CH * CHUNK + Is) * 4 + 1>(xv),
                      val<(CH * CHUNK + Is) * 4 + 2>(xv),
                      val<(CH * CHUNK + Is) * 4 + 3>(xv))),
     ...);
}

// One chunk, fully warp-local: compute -> syncwarp -> transposed coalesced
// write-out. No block barriers anywhere.
// Write-out: lane = rb*8 + c (c in 0..7): 8-lane groups each cover one row's
// 8 float4 = 128B contiguous -> full-sector stores.
// Single-buffer WAR is safe: per-warp smem ops execute in program order, so
// next chunk's STS cannot pass this chunk's LDS.
template<int CH>
__device__ __forceinline__ void do_chunk(const float* xv, float* wbuf, float* lanerow,
                                         float4* out4, size_t wrow0, int lane) {
    constexpr int n4 = (CH == NCHUNK - 1) ? (N_OUT4 - CH * CHUNK) : CHUNK;
    compute_chunk<CH>(xv, lanerow, std::make_integer_sequence<int, n4>{});
    __syncwarp();

    const int c  = lane & 7;       // float4 column within chunk
    const int rb = lane >> 3;      // 0..3 row sub-group
    if (c < n4) {
        #pragma unroll
        for (int it = 0; it < 8; it++) {       // 4 rows per pass * 8 = 32 rows
            int r = it * 4 + rb;
            float4 v = *reinterpret_cast<const float4*>(wbuf + r * RSTRIDE + c * 4);
            __stcs(&out4[(wrow0 + r) * N_OUT4 + CH * CHUNK + c], v);
        }
    }
    __syncwarp();
}

template<int... CHs>
__device__ __forceinline__ void run_chunks(const float* xv, float* wbuf, float* lanerow,
                                           float4* out4, size_t wrow0, int lane,
                                           std::integer_sequence<int, CHs...>) {
    (do_chunk<CHs>(xv, wbuf, lanerow, out4, wrow0, lane), ...);
}

// min-3-CTAs/SM: caps regs at ~85, forcing ptxas to rematerialize shared pair
// products (1 FMUL each from always-live xv) instead of keeping 170 live regs.
// 3 CTAs x 36.9KB smem = 110KB < 228KB carveout, so smem is not the limiter.
__global__ __launch_bounds__(BLOCK, 3)
void algebraic_kernel(const float* __restrict__ x, float* __restrict__ out)
{
    __shared__ float buf[BLOCK * RSTRIDE];   // 36,864 B (8 warp-private regions)

    const int tid  = threadIdx.x;
    const int lane = tid & 31;
    const int wid  = tid >> 5;

    const size_t wrow0 = (size_t)blockIdx.x * BLOCK + wid * 32;  // warp's first row
    const size_t row   = wrow0 + lane;                           // this lane's row

    // Load this lane's row (rows contiguous -> warp reads 2KB contiguous,
    // fully coalesced across the 4 LDG.128).
    float xv[NC];
    const float4* xr = reinterpret_cast<const float4*>(x + row * NC);
    #pragma unroll
    for (int q = 0; q < 4; q++) {
        float4 v = __ldg(xr + q);
        xv[q * 4 + 0] = v.x;
        xv[q * 4 + 1] = v.y;
        xv[q * 4 + 2] = v.z;
        xv[q * 4 + 3] = v.w;
    }

    float* wbuf    = buf + wid * 32 * RSTRIDE;   // warp-private staging
    float* lanerow = wbuf + lane * RSTRIDE;

    run_chunks(xv, wbuf, lanerow, reinterpret_cast<float4*>(out),
               wrow0, lane, std::make_integer_sequence<int, NCHUNK>{});
}

extern "C" void kernel_launch(void* const* d_in, const int* in_sizes, int n_in,
                              void* d_out, int out_size)
{
    const float* x = (const float*)d_in[0];
    float* out = (float*)d_out;

    int n_rows   = in_sizes[0] / NC;      // 262144
    int n_blocks = n_rows / BLOCK;        // 1024

    algebraic_kernel<<<n_blocks, BLOCK>>>(x, out);
}

// round 8
// speedup vs baseline: 1.2495x; 1.2495x over previous
#include <cuda_runtime.h>
#include <utility>
#include <cstdint>

// x[262144, 16] -> out[262144, 696]
// 696 = 16 identity + C(16,2)=120 pairs + C(16,3)=560 triples (lexicographic).
#define NC       16
#define N_OUT4   174      // 696 / 4 float4 per row
#define BLOCK    256      // threads per block == rows per block (8 warps)
#define CHUNK    8        // float4 columns staged per chunk
#define NCHUNK   22       // ceil(174 / 8); last chunk has 6 float4
#define HALF0    11       // chunks handled by even blocks
#define RSTRIDE  36       // floats per staged row (32 data + 4 pad: conflict-free)

// ---------------------------------------------------------------------------
// Compile-time subset index for output column c (lexicographic, matches
// itertools.combinations). j/k == -1 means "absent".
// ---------------------------------------------------------------------------
struct Idx3 { int i, j, k; };

__host__ __device__ constexpr Idx3 col_idx(int c) {
    if (c < NC) return Idx3{c, -1, -1};
    int p = NC;
    for (int i = 0; i < NC; i++)
        for (int j = i + 1; j < NC; j++) {
            if (c == p) return Idx3{i, j, -1};
            p++;
        }
    for (int i = 0; i < NC; i++)
        for (int j = i + 1; j < NC; j++)
            for (int k = j + 1; k < NC; k++) {
                if (c == p) return Idx3{i, j, k};
                p++;
            }
    return Idx3{0, 0, 0};
}

// Product for column C: all-register FMULs, indices folded at compile time.
template<int C>
__device__ __forceinline__ float val(const float* xv) {
    constexpr Idx3 t = col_idx(C);
    float v = xv[t.i];
    if constexpr (t.j >= 0) v *= xv[t.j];
    if constexpr (t.k >= 0) v *= xv[t.k];
    return v;
}

// Compute + stage this lane's row slice for chunk CH.
template<int CH, int... Is>
__device__ __forceinline__ void compute_chunk(const float* xv, float* lanerow,
                                              std::integer_sequence<int, Is...>) {
    ((*reinterpret_cast<float4*>(lanerow + Is * 4) =
          make_float4(val<(CH * CHUNK + Is) * 4 + 0>(xv),
                      val<(CH * CHUNK + Is) * 4 + 1>(xv),
                      val<(CH * CHUNK + Is) * 4 + 2>(xv),
                      val<(CH * CHUNK + Is) * 4 + 3>(xv))),
     ...);
}

// One chunk, fully warp-local: compute -> syncwarp -> transposed coalesced
// write-out (8-lane groups each cover one row's 8 float4 = 128B contiguous).
// Single-buffer WAR is safe: per-warp smem ops execute in program order.
template<int CH>
__device__ __forceinline__ void do_chunk(const float* xv, float* wbuf, float* lanerow,
                                         float4* out4, size_t wrow0, int lane) {
    constexpr int n4 = (CH == NCHUNK - 1) ? (N_OUT4 - CH * CHUNK) : CHUNK;
    compute_chunk<CH>(xv, lanerow, std::make_integer_sequence<int, n4>{});
    __syncwarp();

    const int c  = lane & 7;       // float4 column within chunk
    const int rb = lane >> 3;      // 0..3 row sub-group
    if (c < n4) {
        #pragma unroll
        for (int it = 0; it < 8; it++) {       // 4 rows per pass * 8 = 32 rows
            int r = it * 4 + rb;
            float4 v = *reinterpret_cast<const float4*>(wbuf + r * RSTRIDE + c * 4);
            __stcs(&out4[(wrow0 + r) * N_OUT4 + CH * CHUNK + c], v);
        }
    }
    __syncwarp();
}

// Run chunks OFF .. OFF+sizeof...(CHs)-1.
template<int OFF, int... CHs>
__device__ __forceinline__ void run_chunks(const float* xv, float* wbuf, float* lanerow,
                                           float4* out4, size_t wrow0, int lane,
                                           std::integer_sequence<int, CHs...>) {
    (do_chunk<OFF + CHs>(xv, wbuf, lanerow, out4, wrow0, lane), ...);
}

// Column-split kernel: even blocks compute chunks [0,11), odd blocks [11,22)
// for the same 256 rows. Halved pair-product working set -> natural liveness
// ~100 regs; the (256,2) bound (128 regs) is a roomy cap, not a squeeze.
// 2 CTAs/SM * 36.9KB smem = 74KB < carveout.
__global__ __launch_bounds__(BLOCK, 2)
void algebraic_kernel(const float* __restrict__ x, float* __restrict__ out)
{
    __shared__ float buf[BLOCK * RSTRIDE];   // 36,864 B (8 warp-private regions)

    const int tid  = threadIdx.x;
    const int lane = tid & 31;
    const int wid  = tid >> 5;

    const size_t wrow0 = (size_t)(blockIdx.x >> 1) * BLOCK + wid * 32;
    const size_t row   = wrow0 + lane;

    // Load this lane's row (warp reads 2KB contiguous, fully coalesced).
    // Paired even/odd blocks read the same rows; L2 absorbs the second read.
    float xv[NC];
    const float4* xr = reinterpret_cast<const float4*>(x + row * NC);
    #pragma unroll
    for (int q = 0; q < 4; q++) {
        float4 v = __ldg(xr + q);
        xv[q * 4 + 0] = v.x;
        xv[q * 4 + 1] = v.y;
        xv[q * 4 + 2] = v.z;
        xv[q * 4 + 3] = v.w;
    }

    float* wbuf    = buf + wid * 32 * RSTRIDE;   // warp-private staging
    float* lanerow = wbuf + lane * RSTRIDE;
    float4* out4   = reinterpret_cast<float4*>(out);

    if ((blockIdx.x & 1) == 0) {
        run_chunks<0>(xv, wbuf, lanerow, out4, wrow0, lane,
                      std::make_integer_sequence<int, HALF0>{});
    } else {
        run_chunks<HALF0>(xv, wbuf, lanerow, out4, wrow0, lane,
                          std::make_integer_sequence<int, NCHUNK - HALF0>{});
    }
}

extern "C" void kernel_launch(void* const* d_in, const int* in_sizes, int n_in,
                              void* d_out, int out_size)
{
    const float* x = (const float*)d_in[0];
    float* out = (float*)d_out;

    int n_rows   = in_sizes[0] / NC;          // 262144
    int n_blocks = (n_rows / BLOCK) * 2;      // 2048 (x2 column split)

    algebraic_kernel<<<n_blocks, BLOCK>>>(x, out);
}